// round 4
// baseline (speedup 1.0000x reference)
#include <cuda_runtime.h>

// Fixed problem shapes
#define B_  2048
#define T_  32
#define K_  1024
#define D_  256

#define BM 128            // batch rows per block
#define BN 128            // codes per n-chunk
#define BD 32             // reduction chunk
#define NCHUNK (K_ / BN)  // 8
#define DCHUNK (D_ / BD)  // 8
#define NCI (NCHUNK * DCHUNK)  // 64 chunks total
#define CW  (2 * BN)      // duplicated Cs row width in floats (256)

// Precomputed per-code squared norms: c_sq[t*K + k]
__device__ float g_csq[T_ * K_];

// ---------------------------------------------------------------------------
// packed-fp32 helpers (FFMA2 is PTX-only: fma.rn.f32x2)
// ---------------------------------------------------------------------------
__device__ __forceinline__ void unpack2(unsigned long long v, float& lo, float& hi) {
    asm("mov.b64 {%0, %1}, %2;" : "=f"(lo), "=f"(hi) : "l"(v));
}
__device__ __forceinline__ void ffma2(unsigned long long& d,
                                      unsigned long long a,
                                      unsigned long long b) {
    asm("fma.rn.f32x2 %0, %1, %2, %0;" : "+l"(d) : "l"(a), "l"(b));
}

// ---------------------------------------------------------------------------
// c_sq precompute: one warp per code row (256 floats = 2 float4 per lane)
// ---------------------------------------------------------------------------
__global__ void csq_kernel(const float* __restrict__ cb) {
    int warp = (blockIdx.x * blockDim.x + threadIdx.x) >> 5;
    int lane = threadIdx.x & 31;
    if (warp >= T_ * K_) return;
    const float4* row = (const float4*)(cb + (size_t)warp * D_);
    float s = 0.f;
#pragma unroll
    for (int i = 0; i < 2; i++) {
        float4 v = row[lane + i * 32];
        s += v.x * v.x + v.y * v.y + v.z * v.z + v.w * v.w;
    }
#pragma unroll
    for (int off = 16; off; off >>= 1)
        s += __shfl_down_sync(0xffffffffu, s, off);
    if (lane == 0) g_csq[warp] = s;
}

// ---------------------------------------------------------------------------
// Main kernel: block = (128 batch rows, one t).
//   Xs  [d][m]        128 KB, resident        (a-operands: LDS.64 row pairs)
//   Cs2 [d][2k dup]   2 x 32 KB double-buffer (b-operands: LDS.64 (c,c))
// Codebook streamed in [BD][BN] chunks with register prefetch one chunk ahead.
// 8x8 per-thread microtile as 4 row-pairs x 8 cols of fma.rn.f32x2.
// Running argmin of score = c_sq - 2*dot(x,c)  (x_sq dropped: argmin-invariant).
// ---------------------------------------------------------------------------
extern __shared__ float smem[];

__global__ __launch_bounds__(256) void vsq_kernel(
    const float* __restrict__ x,     // [B, T, D]
    const float* __restrict__ cb,    // [T, K, D]
    float* __restrict__ out)         // [B*T*D embed][B*T idx-as-float]
{
    float* Xs  = smem;                       // [256][128] = 128 KB
    float* Cs0 = smem + D_ * BM;             // [32][256]  =  32 KB (dup cols)
    float* Cs1 = Cs0 + BD * CW;              //  32 KB
    // reduction buffers alias Cs0/Cs1 after the mainloop
    float* red_val = Cs0;                    // [128][16]
    int*   red_idx = (int*)Cs1;              // [128][16]

    __shared__ float s_csq[K_];              // 4 KB
    __shared__ int   s_idx[BM];

    const int t   = blockIdx.y;
    const int b0  = blockIdx.x * BM;
    const int tid = threadIdx.x;

    const float* cbT = cb + (size_t)t * K_ * D_;

    // ---- stage c_sq row for this t ----
#pragma unroll
    for (int i = 0; i < K_ / 256; i++)
        s_csq[tid + i * 256] = g_csq[t * K_ + tid + i * 256];

    // ---- Load X tile transposed: Xs[d][m] (2 threads per row) ----
    {
        const int m    = tid & 127;
        const int half = tid >> 7;           // d range half*128..+127
        const float* xg = x + ((size_t)(b0 + m) * T_ + t) * D_ + half * 128;
#pragma unroll 8
        for (int c4 = 0; c4 < 32; c4++) {
            float4 v = ((const float4*)xg)[c4];
            int d = half * 128 + c4 * 4;
            Xs[(d + 0) * BM + m] = v.x;
            Xs[(d + 1) * BM + m] = v.y;
            Xs[(d + 2) * BM + m] = v.z;
            Xs[(d + 3) * BM + m] = v.w;
        }
    }

    // ---- codebook chunk prefetch state ----
    const int kk = tid & 127;                // code-within-chunk this thread loads
    const int dh = tid >> 7;                 // 0..1 -> d-subrange dh*16..+15
    const int db = dh * 16;
    float4 pf0, pf1, pf2, pf3;

    // prefetch chunk 0 into registers, store duplicated into Cs0
    {
        const float4* cg = (const float4*)(cbT + (size_t)kk * D_ + db);
        pf0 = cg[0]; pf1 = cg[1]; pf2 = cg[2]; pf3 = cg[3];
    }
    {
        float2* dst = (float2*)Cs0 + kk;     // stride CW/2 float2 per d-row
        float v[16] = {pf0.x, pf0.y, pf0.z, pf0.w, pf1.x, pf1.y, pf1.z, pf1.w,
                       pf2.x, pf2.y, pf2.z, pf2.w, pf3.x, pf3.y, pf3.z, pf3.w};
#pragma unroll
        for (int q = 0; q < 16; q++)
            dst[(size_t)(db + q) * (CW / 2)] = make_float2(v[q], v[q]);
    }

    const int tx = tid & 15;                 // col group: cols tx*8 .. +7
    const int ty = tid >> 4;                 // row group: rows ty*8 .. +7
    const int m0 = ty * 8;

    float best_val[8];
    int   best_idx[8];
#pragma unroll
    for (int i = 0; i < 8; i++) { best_val[i] = 3.4e38f; best_idx[i] = 0; }

    int cur = 0;
    for (int nci = 0; nci < NCHUNK; nci++) {
        unsigned long long acc[4][8];        // [row-pair][col]
#pragma unroll
        for (int i = 0; i < 4; i++)
#pragma unroll
            for (int j = 0; j < 8; j++) acc[i][j] = 0ull;

        for (int dci = 0; dci < DCHUNK; dci++) {
            const int ci = nci * DCHUNK + dci;
            __syncthreads();                  // Cs[cur] ready; Cs[cur^1] free

            // issue next chunk's global loads (overlap with compute below)
            if (ci + 1 < NCI) {
                const int nc2 = ((ci + 1) >> 3) * BN;
                const int dc2 = ((ci + 1) & 7) * BD;
                const float4* cg =
                    (const float4*)(cbT + (size_t)(nc2 + kk) * D_ + dc2 + db);
                pf0 = cg[0]; pf1 = cg[1]; pf2 = cg[2]; pf3 = cg[3];
            }

            const float* Csc = cur ? Cs1 : Cs0;
            const int dc = dci * BD;
#pragma unroll 4
            for (int d = 0; d < BD; d++) {
                const double2* brow = (const double2*)(Csc + d * CW + tx * 16);
                double2 b01 = brow[0], b23 = brow[1], b45 = brow[2], b67 = brow[3];
                unsigned long long bb[8] = {
                    __double_as_longlong(b01.x), __double_as_longlong(b01.y),
                    __double_as_longlong(b23.x), __double_as_longlong(b23.y),
                    __double_as_longlong(b45.x), __double_as_longlong(b45.y),
                    __double_as_longlong(b67.x), __double_as_longlong(b67.y)};

                const double2* arow = (const double2*)(Xs + (dc + d) * BM + m0);
                double2 a01 = arow[0], a23 = arow[1];
                unsigned long long aa[4] = {
                    __double_as_longlong(a01.x), __double_as_longlong(a01.y),
                    __double_as_longlong(a23.x), __double_as_longlong(a23.y)};
#pragma unroll
                for (int i = 0; i < 4; i++)
#pragma unroll
                    for (int j = 0; j < 8; j++)
                        ffma2(acc[i][j], aa[i], bb[j]);
            }

            // store prefetched chunk (duplicated) into the other buffer
            if (ci + 1 < NCI) {
                float2* dst = (float2*)(cur ? Cs0 : Cs1) + kk;
                float v[16] = {pf0.x, pf0.y, pf0.z, pf0.w,
                               pf1.x, pf1.y, pf1.z, pf1.w,
                               pf2.x, pf2.y, pf2.z, pf2.w,
                               pf3.x, pf3.y, pf3.z, pf3.w};
#pragma unroll
                for (int q = 0; q < 16; q++)
                    dst[(size_t)(db + q) * (CW / 2)] = make_float2(v[q], v[q]);
            }
            cur ^= 1;
        }

        // ---- scores + running argmin (n ascending per thread) ----
        const int nbase = nci * BN + tx * 8;
#pragma unroll
        for (int j = 0; j < 8; j++) {
            const int n = nbase + j;
            const float cs = s_csq[n];
#pragma unroll
            for (int i = 0; i < 4; i++) {
                float d0, d1;                 // rows m0+2i, m0+2i+1
                unpack2(acc[i][j], d0, d1);
                float s0 = fmaf(-2.f, d0, cs);
                float s1 = fmaf(-2.f, d1, cs);
                if (s0 < best_val[2 * i])     { best_val[2 * i] = s0;     best_idx[2 * i] = n; }
                if (s1 < best_val[2 * i + 1]) { best_val[2 * i + 1] = s1; best_idx[2 * i + 1] = n; }
            }
        }
    }

    // ---- cross-thread argmin reduction (aliases Cs buffers) ----
    __syncthreads();
#pragma unroll
    for (int i = 0; i < 8; i++) {
        red_val[(m0 + i) * 16 + tx] = best_val[i];
        red_idx[(m0 + i) * 16 + tx] = best_idx[i];
    }
    __syncthreads();

    if (tid < BM) {
        float bv = red_val[tid * 16];
        int   bi = red_idx[tid * 16];
#pragma unroll
        for (int j = 1; j < 16; j++) {
            float v  = red_val[tid * 16 + j];
            int   ix = red_idx[tid * 16 + j];
            if (v < bv || (v == bv && ix < bi)) { bv = v; bi = ix; }
        }
        s_idx[tid] = bi;
        // idxes output (as float), shape [B, T], after the embed block
        out[(size_t)B_ * T_ * D_ + (size_t)(b0 + tid) * T_ + t] = (float)bi;
    }
    __syncthreads();

    // ---- embed gather: 2 threads per row, 32 float4 each ----
    {
        const int r = tid >> 1;               // 0..127
        const int p = tid & 1;                // 0..1
        const int kidx = s_idx[r];
        const float4* src = (const float4*)(cbT + (size_t)kidx * D_) + p * 32;
        float4* dst = (float4*)(out + ((size_t)(b0 + r) * T_ + t) * D_) + p * 32;
#pragma unroll 8
        for (int q = 0; q < 32; q++)
            dst[q] = src[q];
    }
}

// ---------------------------------------------------------------------------
extern "C" void kernel_launch(void* const* d_in, const int* in_sizes, int n_in,
                              void* d_out, int out_size) {
    const float* x  = (const float*)d_in[0];   // input   [B, T, D]
    const float* cb = (const float*)d_in[1];   // codebook[T, K, D]
    float* out = (float*)d_out;

    // c_sq precompute: one warp per (t,k) code
    {
        int warps   = T_ * K_;
        int threads = 256;
        int blocks  = (warps * 32 + threads - 1) / threads;
        csq_kernel<<<blocks, threads>>>(cb);
    }

    // main kernel: dynamic smem = Xs(128KB) + 2 x Cs2(32KB) = 192 KB
    {
        size_t shmem = (size_t)(D_ * BM + 2 * BD * CW) * sizeof(float);  // 196608
        cudaFuncSetAttribute(vsq_kernel,
                             cudaFuncAttributeMaxDynamicSharedMemorySize,
                             (int)shmem);
        dim3 grid(B_ / BM, T_);
        vsq_kernel<<<grid, 256, shmem>>>(x, cb, out);
    }
}

// round 8
// speedup vs baseline: 2.7581x; 2.7581x over previous
#include <cuda_runtime.h>

// Fixed problem shapes
#define B_  2048
#define T_  32
#define K_  1024
#define D_  256

#define BM 64             // batch rows per block
#define BN 128            // codes per n-chunk
#define BD 32             // reduction chunk
#define NCHUNK (K_ / BN)  // 8
#define DCHUNK (D_ / BD)  // 8
#define NCI (NCHUNK * DCHUNK)  // 64 chunks

// Precomputed per-code squared norms: c_sq[t*K + k]
__device__ float g_csq[T_ * K_];

typedef unsigned long long ull;

__device__ __forceinline__ ull pack2(float v) {          // (v, v)
    ull r;
    asm("mov.b64 %0, {%1, %1};" : "=l"(r) : "f"(v));
    return r;
}
__device__ __forceinline__ void unpack2(ull v, float& lo, float& hi) {
    asm("mov.b64 {%0, %1}, %2;" : "=f"(lo), "=f"(hi) : "l"(v));
}
__device__ __forceinline__ void ffma2(ull& d, ull a, ull b) {
    asm("fma.rn.f32x2 %0, %1, %2, %0;" : "+l"(d) : "l"(a), "l"(b));
}

// ---------------------------------------------------------------------------
__global__ void csq_kernel(const float* __restrict__ cb) {
    int warp = (blockIdx.x * blockDim.x + threadIdx.x) >> 5;
    int lane = threadIdx.x & 31;
    if (warp >= T_ * K_) return;
    const float4* row = (const float4*)(cb + (size_t)warp * D_);
    float s = 0.f;
#pragma unroll
    for (int i = 0; i < 2; i++) {
        float4 v = row[lane + i * 32];
        s += v.x * v.x + v.y * v.y + v.z * v.z + v.w * v.w;
    }
#pragma unroll
    for (int off = 16; off; off >>= 1)
        s += __shfl_down_sync(0xffffffffu, s, off);
    if (lane == 0) g_csq[warp] = s;
}

// ---------------------------------------------------------------------------
// Block = (64 batch rows, one t). 256 threads, 2 CTAs/SM.
//   Xs [d][m]  64 KB resident. a-loads warp-uniform broadcast (2 LDS.128).
//   Cs [d][k]  2 x 16 KB double buffer, plain row-major: b-load is ONE
//              LDS.128 per thread at lane*16B -> conflict-free.
// Warp w owns rows w*8..w*8+7; lane owns cols lane*4..+3 of each n-chunk.
// Per-thread 8x4 microtile: a gives natural row pairs, b cols duplicated via
// 4 mov.b64. Running argmin of c_sq - 2*dot (x_sq dropped: argmin-invariant).
// ---------------------------------------------------------------------------
extern __shared__ float smem[];

__global__ __launch_bounds__(256, 2) void vsq_kernel(
    const float* __restrict__ x,     // [B, T, D]
    const float* __restrict__ cb,    // [T, K, D]
    float* __restrict__ out)         // [B*T*D embed][B*T idx-as-float]
{
    float* Xs    = smem;                     // [256][64]  = 64 KB
    float* Cs0   = Xs + D_ * BM;             // [32][128]  = 16 KB
    float* Cs1   = Cs0 + BD * BN;            // 16 KB
    float* s_csq = Cs1 + BD * BN;            // [1024] 4 KB
    int*   s_idx = (int*)(s_csq + K_);       // [64]

    const int t   = blockIdx.y;
    const int b0  = blockIdx.x * BM;
    const int tid = threadIdx.x;

    const float* cbT = cb + (size_t)t * K_ * D_;

    // ---- stage c_sq row for this t ----
#pragma unroll
    for (int i = 0; i < K_ / 256; i++)
        s_csq[tid + i * 256] = g_csq[t * K_ + tid + i * 256];

    // ---- Load X tile transposed: Xs[d][m] (4 threads per row) ----
    {
        const int m  = tid & 63;
        const int qd = tid >> 6;             // d-quarter 0..3
        const float4* xg =
            (const float4*)(x + ((size_t)(b0 + m) * T_ + t) * D_ + qd * 64);
#pragma unroll
        for (int j4 = 0; j4 < 16; j4++) {
            float4 v = xg[j4];
            int d = qd * 64 + j4 * 4;
            Xs[(d + 0) * BM + m] = v.x;      // lanes m consecutive: conflict-free
            Xs[(d + 1) * BM + m] = v.y;
            Xs[(d + 2) * BM + m] = v.z;
            Xs[(d + 3) * BM + m] = v.w;
        }
    }

    // ---- codebook chunk staging state ----
    const int kk = tid & 127;                // code within chunk
    const int dh = tid >> 7;                 // 0..1 -> 16 d's each
    float4 pf[4];

    // prefetch + store chunk 0
    {
        const float4* cg = (const float4*)(cbT + (size_t)kk * D_ + dh * 16);
#pragma unroll
        for (int q = 0; q < 4; q++) pf[q] = cg[q];
#pragma unroll
        for (int q = 0; q < 4; q++) {
            int d = dh * 16 + q * 4;
            Cs0[(d + 0) * BN + kk] = pf[q].x;   // lanes kk consecutive: conflict-free
            Cs0[(d + 1) * BN + kk] = pf[q].y;
            Cs0[(d + 2) * BN + kk] = pf[q].z;
            Cs0[(d + 3) * BN + kk] = pf[q].w;
        }
    }

    const int lane = tid & 31;               // cols lane*4 .. +3
    const int wid  = tid >> 5;               // rows wid*8 .. +7
    const int m0   = wid * 8;

    float best_val[8];
    int   best_idx[8];
#pragma unroll
    for (int i = 0; i < 8; i++) { best_val[i] = 3.4e38f; best_idx[i] = 0; }

    int cur = 0;
    for (int nci = 0; nci < NCHUNK; nci++) {
        ull acc[4][4];                        // [row-pair][col]
#pragma unroll
        for (int i = 0; i < 4; i++)
#pragma unroll
            for (int j = 0; j < 4; j++) acc[i][j] = 0ull;

        for (int dci = 0; dci < DCHUNK; dci++) {
            const int ci = nci * DCHUNK + dci;
            __syncthreads();                  // Cs[cur] ready; Cs[cur^1] free

            if (ci + 1 < NCI) {               // prefetch next chunk
                const int nc2 = ((ci + 1) >> 3) * BN;
                const int dc2 = ((ci + 1) & 7) * BD;
                const float4* cg =
                    (const float4*)(cbT + (size_t)(nc2 + kk) * D_ + dc2 + dh * 16);
#pragma unroll
                for (int q = 0; q < 4; q++) pf[q] = cg[q];
            }

            const float* Csc = cur ? Cs1 : Cs0;
            const int dc = dci * BD;
#pragma unroll 4
            for (int d = 0; d < BD; d++) {
                // b: one conflict-free LDS.128; duplicate cols in registers
                float4 bv = *(const float4*)(Csc + d * BN + lane * 4);
                ull bb0 = pack2(bv.x), bb1 = pack2(bv.y);
                ull bb2 = pack2(bv.z), bb3 = pack2(bv.w);

                // a: warp-uniform broadcast loads; natural row pairs
                const double2* arow = (const double2*)(Xs + (dc + d) * BM + m0);
                double2 a01 = arow[0], a23 = arow[1];
                ull aa[4] = {__double_as_longlong(a01.x), __double_as_longlong(a01.y),
                             __double_as_longlong(a23.x), __double_as_longlong(a23.y)};
#pragma unroll
                for (int i = 0; i < 4; i++) {
                    ffma2(acc[i][0], aa[i], bb0);
                    ffma2(acc[i][1], aa[i], bb1);
                    ffma2(acc[i][2], aa[i], bb2);
                    ffma2(acc[i][3], aa[i], bb3);
                }
            }

            if (ci + 1 < NCI) {               // store prefetched chunk
                float* dst = cur ? Cs0 : Cs1;
#pragma unroll
                for (int q = 0; q < 4; q++) {
                    int d = dh * 16 + q * 4;
                    dst[(d + 0) * BN + kk] = pf[q].x;
                    dst[(d + 1) * BN + kk] = pf[q].y;
                    dst[(d + 2) * BN + kk] = pf[q].z;
                    dst[(d + 3) * BN + kk] = pf[q].w;
                }
            }
            cur ^= 1;
        }

        // ---- scores + running argmin (n ascending per thread) ----
        const int nbase = nci * BN + lane * 4;
#pragma unroll
        for (int j = 0; j < 4; j++) {
            const int n = nbase + j;
            const float cs = s_csq[n];
#pragma unroll
            for (int i = 0; i < 4; i++) {
                float d0, d1;                 // rows m0+2i, m0+2i+1
                unpack2(acc[i][j], d0, d1);
                float s0 = fmaf(-2.f, d0, cs);
                float s1 = fmaf(-2.f, d1, cs);
                if (s0 < best_val[2 * i])     { best_val[2 * i] = s0;     best_idx[2 * i] = n; }
                if (s1 < best_val[2 * i + 1]) { best_val[2 * i + 1] = s1; best_idx[2 * i + 1] = n; }
            }
        }
    }

    // ---- argmin across lanes: pure warp shuffle (warp owns its 8 rows) ----
#pragma unroll
    for (int i = 0; i < 8; i++) {
        float bv = best_val[i];
        int   bi = best_idx[i];
#pragma unroll
        for (int off = 16; off; off >>= 1) {
            float ov = __shfl_down_sync(0xffffffffu, bv, off);
            int   oi = __shfl_down_sync(0xffffffffu, bi, off);
            if (ov < bv || (ov == bv && oi < bi)) { bv = ov; bi = oi; }
        }
        if (lane == 0) {
            s_idx[m0 + i] = bi;
            out[(size_t)B_ * T_ * D_ + (size_t)(b0 + m0 + i) * T_ + t] = (float)bi;
        }
    }
    __syncthreads();

    // ---- embed gather: 4 threads per row, 16 float4 each ----
    {
        const int r = tid >> 2;               // 0..63
        const int p = tid & 3;                // 0..3
        const int kidx = s_idx[r];
        const float4* src = (const float4*)(cbT + (size_t)kidx * D_) + p * 16;
        float4* dst = (float4*)(out + ((size_t)(b0 + r) * T_ + t) * D_) + p * 16;
#pragma unroll
        for (int q = 0; q < 16; q++)
            dst[q] = src[q];
    }
}

// ---------------------------------------------------------------------------
extern "C" void kernel_launch(void* const* d_in, const int* in_sizes, int n_in,
                              void* d_out, int out_size) {
    const float* x  = (const float*)d_in[0];   // input   [B, T, D]
    const float* cb = (const float*)d_in[1];   // codebook[T, K, D]
    float* out = (float*)d_out;

    {
        int warps   = T_ * K_;
        int threads = 256;
        int blocks  = (warps * 32 + threads - 1) / threads;
        csq_kernel<<<blocks, threads>>>(cb);
    }

    {
        // Xs 64KB + 2x Cs 16KB + csq 4KB + s_idx
        size_t shmem = (size_t)(D_ * BM + 2 * BD * BN + K_) * sizeof(float)
                     + BM * sizeof(int);      // 102656 B -> 2 CTAs/SM
        cudaFuncSetAttribute(vsq_kernel,
                             cudaFuncAttributeMaxDynamicSharedMemorySize,
                             (int)shmem);
        dim3 grid(B_ / BM, T_);
        vsq_kernel<<<grid, 256, shmem>>>(x, cb, out);
    }
}